// round 16
// baseline (speedup 1.0000x reference)
#include <cuda_runtime.h>
#include <cuda_fp16.h>
#include <cuda_bf16.h>
#include <math_constants.h>
#include <cstdint>

// Problem constants
#define T_TOK   2048
#define D_MODEL 1024
#define HIDDEN  4096
#define N_EXP   8
// TOP_K = 2

// GEMM tiling (fp16): CTA 128x128, 4 warps (2x2), warp tile 64x64
#define BM 128
#define BN 128
#define BK 64                       // fp16 elems per k-chunk => 128B rows
#define NCH (D_MODEL / BK)          // 16
#define TILE_B 16384                // 128 rows x 128 bytes per operand buffer
#define STAGES 3

// GEMM grid: x = mtile (16), y = ntile (32) + 1 lbal slice, z = expert (8)
// z is the slowest-varying dispatch index: expert e's CTAs are all dispatched
// before expert e+1's -> the convert(e+1)-then-spin(e) chain is deadlock-free.
#define GRID_X 16
#define GRID_Y 33
#define GRID_Z 8
#define TOTAL_CTAS (GRID_X * GRID_Y * GRID_Z)   // 4224
#define TILES_PER_EXP (GRID_X * 32)             // 512 conversion slices

// per-expert weight sizes
#define EXP_FLOATS (HIDDEN * D_MODEL)           // 4,194,304 floats per expert
#define SLICE_FLOATS (EXP_FLOATS / TILES_PER_EXP)   // 8192 floats per GEMM CTA

// prep-kernel grid partition (conv covers expert 0 ONLY)
#define NB_ROUTER 2048                                  // one block per token
#define NB_CONV0  (EXP_FLOATS / (256 * 8))              // 2048
#define NB_ZERO   ((T_TOK * HIDDEN) / (256 * 4))        // 8192
#define NB_PREP   (NB_ROUTER + NB_CONV0 + NB_ZERO)      // 12288

// ---------------- device scratch (allocation-free) ----------------
// All counters start zero (module load) and are re-zeroed by the last GEMM
// CTA each run, so every graph replay starts clean.
__device__ int    g_count[N_EXP];        // router: tokens per expert
__device__ int    g_conv[N_EXP];         // conversion publications per expert
__device__ int    g_done;                // exit tickets
__device__ int    g_tok[N_EXP * T_TOK];  // packed token*2 + slot
__device__ float  g_wt [N_EXP * T_TOK];
__device__ float  g_probs[T_TOK * N_EXP];
__device__ __half g_w1h[(size_t)N_EXP * HIDDEN * D_MODEL]; // 64 MB fp16 weights
__device__ __half g_xh [(size_t)T_TOK * D_MODEL];          // 4 MB fp16 activations

// ---------------- helpers ----------------
__device__ __forceinline__ uint32_t smem_u32(const void* p) {
    uint32_t a;
    asm("{ .reg .u64 t; cvta.to.shared.u64 t, %1; cvt.u32.u64 %0, t; }" : "=r"(a) : "l"(p));
    return a;
}

__device__ __forceinline__ void cp16(uint32_t dst, const void* src, int sz) {
    asm volatile("cp.async.cg.shared.global [%0], [%1], 16, %2;"
                 :: "r"(dst), "l"(src), "r"(sz) : "memory");
}

#define LDSM4(r, addr) \
    asm volatile("ldmatrix.sync.aligned.m8n8.x4.shared.b16 {%0,%1,%2,%3}, [%4];" \
                 : "=r"((r)[0]), "=r"((r)[1]), "=r"((r)[2]), "=r"((r)[3]) : "r"(addr))

__device__ __forceinline__ void mma_f16(float* d, const uint32_t* a, const uint32_t* b) {
    asm volatile(
        "mma.sync.aligned.m16n8k16.row.col.f32.f16.f16.f32 "
        "{%0,%1,%2,%3}, {%4,%5,%6,%7}, {%8,%9}, {%0,%1,%2,%3};"
        : "+f"(d[0]), "+f"(d[1]), "+f"(d[2]), "+f"(d[3])
        : "r"(a[0]), "r"(a[1]), "r"(a[2]), "r"(a[3]), "r"(b[0]), "r"(b[1]));
}

// vectorized global float2 reduction (PTX ISA 8.1, sm_90+)
__device__ __forceinline__ void red_add2(float* addr, float x, float y) {
    asm volatile("red.global.add.v2.f32 [%0], {%1, %2};"
                 :: "l"(addr), "f"(x), "f"(y) : "memory");
}

// release-publish: make prior writes visible, then bump the counter
__device__ __forceinline__ void publish(int* ctr) {
    __threadfence();
    atomicAdd(ctr, 1);
}

// acquire-spin: wait until *ctr >= target, then fence so later reads see data
__device__ __forceinline__ void spin_until(int* ctr, int target) {
    while (atomicAdd(ctr, 0) < target) __nanosleep(128);
    __threadfence();
}

// per-CTA exit ticket: the last of TOTAL_CTAS GEMM CTAs resets all run state
// for the next graph replay. Safe: g_conv[e] publications all precede the
// last ticket (expert-7 CTAs spin on g_conv[7] before exiting; g_conv[0] is
// published by prep, which precedes the GEMM on the stream).
__device__ __forceinline__ void exit_ticket(int tid) {
    if (tid == 0) {
        int v = atomicAdd(&g_done, 1);
        if (v == TOTAL_CTAS - 1) {
            #pragma unroll
            for (int e = 0; e < N_EXP; e++) { g_count[e] = 0; g_conv[e] = 0; }
            g_done = 0;
        }
    }
}

// convert 8 contiguous fp32 -> 8 fp16 (one uint4 store)
__device__ __forceinline__ void conv8(const float* __restrict__ src, __half* __restrict__ dst) {
    float4 f0 = *(const float4*)(src);
    float4 f1 = *(const float4*)(src + 4);
    union { __half2 h[4]; uint4 u; } p;
    p.h[0] = __floats2half2_rn(f0.x, f0.y);
    p.h[1] = __floats2half2_rn(f0.z, f0.w);
    p.h[2] = __floats2half2_rn(f1.x, f1.y);
    p.h[3] = __floats2half2_rn(f1.z, f1.w);
    *(uint4*)(dst) = p.u;
}

// ---------------- kernel 1: fused prep ----------------
// Grid partition (one launch overlaps all independent pre-work, zero streams):
//   blocks [0, 2048)         : router for token b (+ fused x->fp16 by warp 0)
//   blocks [2048, 4096)      : expert-0 w1 fp32->fp16 (publishes g_conv[0])
//   blocks [4096, 12288)     : zero the output buffer
// Experts 1-7 are converted inside the GEMM kernel (overlapped).
__global__ __launch_bounds__(256) void prep_kernel(
    const float* __restrict__ x, const float* __restrict__ rw,
    const float* __restrict__ w1, float* __restrict__ out)
{
    const int b = blockIdx.x;

    if (b >= NB_ROUTER + NB_CONV0) {           // ---- zero-out branch ----
        size_t i = ((size_t)(b - NB_ROUTER - NB_CONV0) * 256 + threadIdx.x) * 4;
        *(float4*)(out + i) = make_float4(0.f, 0.f, 0.f, 0.f);
        return;
    }

    if (b >= NB_ROUTER) {                      // ---- expert-0 conversion ----
        size_t i = ((size_t)(b - NB_ROUTER) * 256 + threadIdx.x) * 8;
        conv8(w1 + i, g_w1h + i);
        __syncthreads();
        if (threadIdx.x == 0) publish(&g_conv[0]);
        return;
    }

    // ---- router branch (R13 version: 8 warps, one per expert) ----
    int t    = b;
    int warp = threadIdx.x >> 5;
    int lane = threadIdx.x & 31;

    const float4* xv = (const float4*)(x + (size_t)t * D_MODEL);
    const float4* wv = (const float4*)(rw + (size_t)warp * D_MODEL);
    float s = 0.f;
    #pragma unroll
    for (int i = 0; i < 8; i++) {
        float4 a = xv[lane + i * 32];
        float4 w = wv[lane + i * 32];
        s += a.x * w.x + a.y * w.y + a.z * w.z + a.w * w.w;
        if (warp == 0) {   // warp 0 sees the full row: convert x to fp16 once
            __half2 h0 = __floats2half2_rn(a.x, a.y);
            __half2 h1 = __floats2half2_rn(a.z, a.w);
            *(__half2*)(g_xh + (size_t)t * D_MODEL + (lane + i * 32) * 4)     = h0;
            *(__half2*)(g_xh + (size_t)t * D_MODEL + (lane + i * 32) * 4 + 2) = h1;
        }
    }
    #pragma unroll
    for (int o = 16; o > 0; o >>= 1) s += __shfl_xor_sync(0xffffffffu, s, o);

    __shared__ float logits[N_EXP];
    if (lane == 0) logits[warp] = s;
    __syncthreads();

    if (threadIdx.x == 0) {
        int e0 = 0; float v0 = logits[0];
        #pragma unroll
        for (int e = 1; e < N_EXP; e++) if (logits[e] > v0) { v0 = logits[e]; e0 = e; }
        int e1 = -1; float v1 = -CUDART_INF_F;
        #pragma unroll
        for (int e = 0; e < N_EXP; e++) if (e != e0 && logits[e] > v1) { v1 = logits[e]; e1 = e; }

        float ex1 = expf(v1 - v0);
        float inv = 1.0f / (1.0f + ex1);
        float c0 = inv, c1 = ex1 * inv;

        int p0 = atomicAdd(&g_count[e0], 1);
        g_tok[e0 * T_TOK + p0] = t * 2 + 0;
        g_wt [e0 * T_TOK + p0] = c0;
        int p1 = atomicAdd(&g_count[e1], 1);
        g_tok[e1 * T_TOK + p1] = t * 2 + 1;
        g_wt [e1 * T_TOK + p1] = c1;

        float mx = v0;
        float pe[N_EXP], se = 0.f;
        #pragma unroll
        for (int e = 0; e < N_EXP; e++) { pe[e] = expf(logits[e] - mx); se += pe[e]; }
        float invs = 1.0f / se;
        #pragma unroll
        for (int e = 0; e < N_EXP; e++) g_probs[t * N_EXP + e] = pe[e] * invs;
    }
}

// ---------------- kernel 2: GEMM + inline next-expert conversion ----------------
// y in [0,32): GEMM tile of expert z. Flow:
//   1. convert slice (y*16+x) of expert z+1's weights, publish g_conv[z+1]
//      (BEFORE any spin -> liveness via in-order z dispatch)
//   2. spin on g_conv[z] (target 2048 for z==0 from prep, else 512)
//   3. measured-best mainloop (4 warps 2x2, 64x64 warp tile, 3-stage cp.async,
//      single sync per chunk, interleaved B-frag/MMA), red.v2 epilogue.
// y == 32: one CTA computes l_bal; no conversion (keeps the 512 count exact).
// Every CTA takes an exit ticket; the last resets g_count/g_conv/g_done.
__global__ void __launch_bounds__(128, 2) moe_gemm_h(
    const float* __restrict__ w1, const float* __restrict__ b1,
    float* __restrict__ out, int want_lbal)
{
    const int tid = threadIdx.x;
    const int e   = blockIdx.z;

    // ---------------- l_bal slice ----------------
    if (blockIdx.y == 32) {
        if (blockIdx.x == 0 && blockIdx.z == 0 && want_lbal) {
            float s = 0.f;
            #pragma unroll 8
            for (int k = 0; k < (T_TOK * N_EXP) / 128; k++)
                s += g_probs[tid + k * 128];
            __shared__ float red[128];
            red[tid] = s;
            __syncthreads();
            #pragma unroll
            for (int off = 64; off >= 8; off >>= 1) {
                if (tid < off) red[tid] += red[tid + off];
                __syncthreads();
            }
            if (tid == 0) {
                float l = 0.f;
                #pragma unroll
                for (int ee = 0; ee < N_EXP; ee++) {
                    float f = (float)g_count[ee] / (float)T_TOK;
                    l += f * (red[ee] / (float)T_TOK);
                }
                out[(size_t)T_TOK * HIDDEN] = (float)N_EXP * l;
            }
        }
        __syncthreads();
        exit_ticket(tid);
        return;
    }

    // ---------------- step 1: convert next expert's slice ----------------
    if (e + 1 < N_EXP) {
        const int slice = blockIdx.y * GRID_X + blockIdx.x;      // 0..511
        size_t base = (size_t)(e + 1) * EXP_FLOATS + (size_t)slice * SLICE_FLOATS;
        #pragma unroll
        for (int it = 0; it < 8; it++) {                         // 8 x 1024 floats
            size_t i = base + (size_t)it * 1024 + (size_t)tid * 8;
            conv8(w1 + i, g_w1h + i);
        }
        __syncthreads();
        if (tid == 0) publish(&g_conv[e + 1]);
    }

    // ---------------- step 2: routing metadata + weight-ready spin ----------
    const int cnt = g_count[e];
    const int m0  = blockIdx.x * BM;
    if (m0 >= cnt) {
        __syncthreads();            // all warps have read g_count before ticket
        exit_ticket(tid);
        return;
    }
    const int n0  = blockIdx.y * BN;

    extern __shared__ __half hsm[];
    const uint32_t uS = smem_u32(hsm);

    __shared__ int   s_tok[BM];
    __shared__ float s_w[BM];
    __shared__ float s_bias[BN];

    const int wid = tid >> 5;
    const int lid = tid & 31;
    const int wm  = (wid >> 1) * 64;
    const int wn  = (wid & 1) * 64;

    {
        int r = m0 + tid;
        if (r < cnt) { s_tok[tid] = g_tok[e * T_TOK + r]; s_w[tid] = g_wt[e * T_TOK + r]; }
        else         { s_tok[tid] = -1;                   s_w[tid] = 0.f; }
        s_bias[tid] = b1[(size_t)e * HIDDEN + n0 + tid];
    }
    if (tid == 0) spin_until(&g_conv[e], (e == 0) ? NB_CONV0 : TILES_PER_EXP);
    __syncthreads();

    const __half* w1base = g_w1h + ((size_t)e * HIDDEN + n0) * D_MODEL;

    auto stage = [&](int buf, int k0) {
        const uint32_t ab = uS + (uint32_t)buf * 2 * TILE_B;
        const uint32_t bb = ab + TILE_B;
        #pragma unroll
        for (int i = 0; i < 8; i++) {
            int idx = tid + i * 128;
            int row = idx >> 3;
            int ch  = idx & 7;
            uint32_t soff = (uint32_t)(row * 128 + ((ch ^ (row & 7)) << 4));

            int pk  = s_tok[row];
            int tok = pk >= 0 ? (pk >> 1) : 0;
            cp16(ab + soff, g_xh + (size_t)tok * D_MODEL + k0 + ch * 8, pk >= 0 ? 16 : 0);
            cp16(bb + soff, w1base + (size_t)row * D_MODEL + k0 + ch * 8, 16);
        }
        asm volatile("cp.async.commit_group;" ::: "memory");
    };

    float acc[4][8][4];
    #pragma unroll
    for (int mt = 0; mt < 4; mt++)
        #pragma unroll
        for (int nt = 0; nt < 8; nt++)
            #pragma unroll
            for (int q = 0; q < 4; q++) acc[mt][nt][q] = 0.f;

    stage(0, 0);
    stage(1, BK);

    const int l8   = lid & 7;
    const int jA_m = ((lid >> 3) & 1) * 8;
    const int jA_k = (lid >> 4) & 1;
    const int jB_n = ((lid >> 4) & 1) * 8;
    const int jB_k = (lid >> 3) & 1;

    for (int c = 0; c < NCH; ++c) {
        asm volatile("cp.async.wait_group 1;" ::: "memory");
        __syncthreads();

        if (c + 2 < NCH) stage((c + 2) % STAGES, (c + 2) * BK);
        else asm volatile("cp.async.commit_group;" ::: "memory");  // keep 2 groups in flight

        const uint32_t ab = uS + (uint32_t)(c % STAGES) * 2 * TILE_B;
        const uint32_t bb = ab + TILE_B;

        #pragma unroll
        for (int s = 0; s < 4; s++) {
            uint32_t a[4][4];
            #pragma unroll
            for (int mt = 0; mt < 4; mt++) {
                int row = wm + mt * 16 + jA_m + l8;
                int ch  = 2 * s + jA_k;
                LDSM4(a[mt], ab + (uint32_t)(row * 128 + ((ch ^ (row & 7)) << 4)));
            }
            // interleave: load each B fragment, immediately issue its 8 MMAs
            #pragma unroll
            for (int bg = 0; bg < 4; bg++) {
                uint32_t bfr[4];
                int row = wn + bg * 16 + jB_n + l8;
                int ch  = 2 * s + jB_k;
                LDSM4(bfr, bb + (uint32_t)(row * 128 + ((ch ^ (row & 7)) << 4)));
                #pragma unroll
                for (int mt = 0; mt < 4; mt++) {
                    mma_f16(acc[mt][2 * bg + 0], a[mt], bfr + 0);
                    mma_f16(acc[mt][2 * bg + 1], a[mt], bfr + 2);
                }
            }
        }
    }

    const int lr = lid >> 2;
    const int lc = lid & 3;
    #pragma unroll
    for (int mt = 0; mt < 4; mt++) {
        int r_lo = wm + mt * 16 + lr;
        int r_hi = r_lo + 8;
        if ((m0 + r_lo) < cnt) {
            int   tok = s_tok[r_lo] >> 1;
            float wt  = s_w[r_lo];
            float* dst = out + (size_t)tok * HIDDEN + n0;
            #pragma unroll
            for (int nt = 0; nt < 8; nt++) {
                int col = wn + nt * 8 + lc * 2;
                red_add2(dst + col, wt * (acc[mt][nt][0] + s_bias[col]),
                                    wt * (acc[mt][nt][1] + s_bias[col + 1]));
            }
        }
        if ((m0 + r_hi) < cnt) {
            int   tok = s_tok[r_hi] >> 1;
            float wt  = s_w[r_hi];
            float* dst = out + (size_t)tok * HIDDEN + n0;
            #pragma unroll
            for (int nt = 0; nt < 8; nt++) {
                int col = wn + nt * 8 + lc * 2;
                red_add2(dst + col, wt * (acc[mt][nt][2] + s_bias[col]),
                                    wt * (acc[mt][nt][3] + s_bias[col + 1]));
            }
        }
    }

    __syncthreads();                // all warps done (reads + REDs issued)
    exit_ticket(tid);
}

// ---------------- launch ----------------
extern "C" void kernel_launch(void* const* d_in, const int* in_sizes, int n_in,
                              void* d_out, int out_size)
{
    const float* x  = (const float*)d_in[0];   // [1,2048,1024]
    const float* rw = (const float*)d_in[1];   // [8,1024]
    const float* w1 = (const float*)d_in[2];   // [8,4096,1024]
    const float* b1 = (const float*)d_in[3];   // [8,4096]
    float* out = (float*)d_out;

    static bool smem_set = false;
    if (!smem_set) {
        cudaFuncSetAttribute(moe_gemm_h, cudaFuncAttributeMaxDynamicSharedMemorySize,
                             STAGES * 2 * TILE_B);
        smem_set = true;
    }

    prep_kernel<<<NB_PREP, 256>>>(x, rw, w1, out);

    size_t total = (size_t)T_TOK * HIDDEN;
    int want_lbal = ((size_t)out_size > total) ? 1 : 0;

    dim3 gemm_grid(GRID_X, GRID_Y, GRID_Z);   // 16 mtiles, 32 ntiles + lbal slice, 8 experts
    moe_gemm_h<<<gemm_grid, 128, STAGES * 2 * TILE_B>>>(w1, b1, out, want_lbal);
}

// round 17
// speedup vs baseline: 1.1128x; 1.1128x over previous
#include <cuda_runtime.h>
#include <cuda_fp16.h>
#include <cuda_bf16.h>
#include <math_constants.h>
#include <cstdint>

// Problem constants
#define T_TOK   2048
#define D_MODEL 1024
#define HIDDEN  4096
#define N_EXP   8
// TOP_K = 2

// GEMM tiling (fp16): CTA 128x128, 4 warps (2x2), warp tile 64x64
#define BM 128
#define BN 128
#define BK 64                       // fp16 elems per k-chunk => 128B rows
#define NCH (D_MODEL / BK)          // 16
#define TILE_B 16384                // 128 rows x 128 bytes per operand buffer
#define STAGES 3

// GEMM grid: x = mtile (16), y = ntile (32) + 1 lbal slice, z = expert (8)
#define GRID_X 16
#define GRID_Y 33
#define GRID_Z 8
#define TOTAL_CTAS (GRID_X * GRID_Y * GRID_Z)   // 4224

// prep-kernel grid partition
#define NB_ROUTER 2048                                  // one block per token
#define NB_CONV   ((N_EXP * HIDDEN * D_MODEL) / (256 * 8))   // 4096
#define NB_ZERO   ((T_TOK * HIDDEN) / (256 * 4))             // 8192
#define NB_PREP   (NB_ROUTER + NB_CONV + NB_ZERO)            // 14336

// ---------------- device scratch (allocation-free) ----------------
// g_count/g_done start zero (module load) and are re-zeroed by the last GEMM
// CTA each run, so every graph replay starts clean.
__device__ int    g_count[N_EXP];
__device__ int    g_done;
__device__ int    g_tok[N_EXP * T_TOK];              // packed token*2 + slot
__device__ float  g_wt [N_EXP * T_TOK];
__device__ float  g_probs[T_TOK * N_EXP];
__device__ __half g_w1h[(size_t)N_EXP * HIDDEN * D_MODEL]; // 64 MB fp16 weights
__device__ __half g_xh [(size_t)T_TOK * D_MODEL];          // 4 MB fp16 activations

// ---------------- helpers ----------------
__device__ __forceinline__ uint32_t smem_u32(const void* p) {
    uint32_t a;
    asm("{ .reg .u64 t; cvta.to.shared.u64 t, %1; cvt.u32.u64 %0, t; }" : "=r"(a) : "l"(p));
    return a;
}

__device__ __forceinline__ void cp16(uint32_t dst, const void* src, int sz) {
    asm volatile("cp.async.cg.shared.global [%0], [%1], 16, %2;"
                 :: "r"(dst), "l"(src), "r"(sz) : "memory");
}

#define LDSM4(r, addr) \
    asm volatile("ldmatrix.sync.aligned.m8n8.x4.shared.b16 {%0,%1,%2,%3}, [%4];" \
                 : "=r"((r)[0]), "=r"((r)[1]), "=r"((r)[2]), "=r"((r)[3]) : "r"(addr))

__device__ __forceinline__ void mma_f16(float* d, const uint32_t* a, const uint32_t* b) {
    asm volatile(
        "mma.sync.aligned.m16n8k16.row.col.f32.f16.f16.f32 "
        "{%0,%1,%2,%3}, {%4,%5,%6,%7}, {%8,%9}, {%0,%1,%2,%3};"
        : "+f"(d[0]), "+f"(d[1]), "+f"(d[2]), "+f"(d[3])
        : "r"(a[0]), "r"(a[1]), "r"(a[2]), "r"(a[3]), "r"(b[0]), "r"(b[1]));
}

// vectorized global float2 reduction (PTX ISA 8.1, sm_90+)
__device__ __forceinline__ void red_add2(float* addr, float x, float y) {
    asm volatile("red.global.add.v2.f32 [%0], {%1, %2};"
                 :: "l"(addr), "f"(x), "f"(y) : "memory");
}

// per-CTA exit ticket: the last of TOTAL_CTAS CTAs resets routing state for
// the next graph replay. Each CTA increments exactly once (tid 0), and only
// after all of its warps are done reading g_count.
__device__ __forceinline__ void exit_ticket(int tid) {
    if (tid == 0) {
        int v = atomicAdd(&g_done, 1);
        if (v == TOTAL_CTAS - 1) {
            #pragma unroll
            for (int e = 0; e < N_EXP; e++) g_count[e] = 0;
            g_done = 0;
        }
    }
}

// ---------------- kernel 1: fused prep ----------------
// Grid partition (one launch overlaps all independent pre-work, zero streams):
//   blocks [0, 2048)         : router for token b (+ fused x->fp16 by warp 0)
//   blocks [2048, 6144)      : w1 fp32->fp16 conversion
//   blocks [6144, 14336)     : zero the output buffer
__global__ __launch_bounds__(256) void prep_kernel(
    const float* __restrict__ x, const float* __restrict__ rw,
    const float* __restrict__ w1, float* __restrict__ out)
{
    const int b = blockIdx.x;

    if (b >= NB_ROUTER + NB_CONV) {            // ---- zero-out branch ----
        size_t i = ((size_t)(b - NB_ROUTER - NB_CONV) * 256 + threadIdx.x) * 4;
        *(float4*)(out + i) = make_float4(0.f, 0.f, 0.f, 0.f);
        return;
    }

    if (b >= NB_ROUTER) {                      // ---- w1 conversion branch ----
        size_t i = ((size_t)(b - NB_ROUTER) * 256 + threadIdx.x) * 8;
        float4 f0 = *(const float4*)(w1 + i);
        float4 f1 = *(const float4*)(w1 + i + 4);
        union { __half2 h[4]; uint4 u; } p;
        p.h[0] = __floats2half2_rn(f0.x, f0.y);
        p.h[1] = __floats2half2_rn(f0.z, f0.w);
        p.h[2] = __floats2half2_rn(f1.x, f1.y);
        p.h[3] = __floats2half2_rn(f1.z, f1.w);
        *(uint4*)(g_w1h + i) = p.u;
        return;
    }

    // ---- router branch ----
    int t    = b;
    int warp = threadIdx.x >> 5;
    int lane = threadIdx.x & 31;

    const float4* xv = (const float4*)(x + (size_t)t * D_MODEL);
    const float4* wv = (const float4*)(rw + (size_t)warp * D_MODEL);
    float s = 0.f;
    #pragma unroll
    for (int i = 0; i < 8; i++) {
        float4 a = xv[lane + i * 32];
        float4 w = wv[lane + i * 32];
        s += a.x * w.x + a.y * w.y + a.z * w.z + a.w * w.w;
        if (warp == 0) {   // warp 0 sees the full row: convert x to fp16 once
            __half2 h0 = __floats2half2_rn(a.x, a.y);
            __half2 h1 = __floats2half2_rn(a.z, a.w);
            *(__half2*)(g_xh + (size_t)t * D_MODEL + (lane + i * 32) * 4)     = h0;
            *(__half2*)(g_xh + (size_t)t * D_MODEL + (lane + i * 32) * 4 + 2) = h1;
        }
    }
    #pragma unroll
    for (int o = 16; o > 0; o >>= 1) s += __shfl_xor_sync(0xffffffffu, s, o);

    __shared__ float logits[N_EXP];
    if (lane == 0) logits[warp] = s;
    __syncthreads();

    if (threadIdx.x == 0) {
        int e0 = 0; float v0 = logits[0];
        #pragma unroll
        for (int e = 1; e < N_EXP; e++) if (logits[e] > v0) { v0 = logits[e]; e0 = e; }
        int e1 = -1; float v1 = -CUDART_INF_F;
        #pragma unroll
        for (int e = 0; e < N_EXP; e++) if (e != e0 && logits[e] > v1) { v1 = logits[e]; e1 = e; }

        float ex1 = expf(v1 - v0);
        float inv = 1.0f / (1.0f + ex1);
        float c0 = inv, c1 = ex1 * inv;

        int p0 = atomicAdd(&g_count[e0], 1);
        g_tok[e0 * T_TOK + p0] = t * 2 + 0;
        g_wt [e0 * T_TOK + p0] = c0;
        int p1 = atomicAdd(&g_count[e1], 1);
        g_tok[e1 * T_TOK + p1] = t * 2 + 1;
        g_wt [e1 * T_TOK + p1] = c1;

        float mx = v0;
        float pe[N_EXP], se = 0.f;
        #pragma unroll
        for (int e = 0; e < N_EXP; e++) { pe[e] = expf(logits[e] - mx); se += pe[e]; }
        float invs = 1.0f / se;
        #pragma unroll
        for (int e = 0; e < N_EXP; e++) g_probs[t * N_EXP + e] = pe[e] * invs;
    }
}

// ---------------- kernel 2: GEMM + folded l_bal + self-reset ----------------
// y in [0,32): fp16 m16n8k16 grouped expert GEMM tile (measured-best config:
//   CTA 128x128, 4 warps 2x2, warp tile 64x64, 3-stage cp.async pipeline,
//   single __syncthreads per chunk, B-frag loads interleaved with MMA issue).
// y == 32: one CTA (x=0,z=0) computes the l_bal scalar concurrently.
// Every CTA takes an exit ticket; the last one resets g_count/g_done.
// Epilogue: wt*(acc+bias) red.v2-added into zeroed output (exactly 2
// contributions per element, fp add commutative -> bitwise deterministic).
__global__ void __launch_bounds__(128, 2) moe_gemm_h(
    const float* __restrict__ b1, float* __restrict__ out, int want_lbal)
{
    const int tid = threadIdx.x;

    // ---------------- l_bal slice ----------------
    if (blockIdx.y == 32) {
        if (blockIdx.x == 0 && blockIdx.z == 0 && want_lbal) {
            float s = 0.f;
            #pragma unroll 8
            for (int k = 0; k < (T_TOK * N_EXP) / 128; k++)
                s += g_probs[tid + k * 128];
            __shared__ float red[128];
            red[tid] = s;
            __syncthreads();
            #pragma unroll
            for (int off = 64; off >= 8; off >>= 1) {
                if (tid < off) red[tid] += red[tid + off];
                __syncthreads();
            }
            if (tid == 0) {
                float l = 0.f;
                #pragma unroll
                for (int e = 0; e < N_EXP; e++) {
                    float f = (float)g_count[e] / (float)T_TOK;
                    l += f * (red[e] / (float)T_TOK);
                }
                out[(size_t)T_TOK * HIDDEN] = (float)N_EXP * l;
            }
        }
        __syncthreads();
        exit_ticket(tid);
        return;
    }

    // ---------------- GEMM slice ----------------
    const int e   = blockIdx.z;
    const int cnt = g_count[e];
    const int m0  = blockIdx.x * BM;
    if (m0 >= cnt) {
        __syncthreads();            // all warps have read g_count before ticket
        exit_ticket(tid);
        return;
    }
    const int n0  = blockIdx.y * BN;

    extern __shared__ __half hsm[];
    const uint32_t uS = smem_u32(hsm);

    __shared__ int   s_tok[BM];
    __shared__ float s_w[BM];
    __shared__ float s_bias[BN];

    const int wid = tid >> 5;
    const int lid = tid & 31;
    const int wm  = (wid >> 1) * 64;
    const int wn  = (wid & 1) * 64;

    {
        int r = m0 + tid;
        if (r < cnt) { s_tok[tid] = g_tok[e * T_TOK + r]; s_w[tid] = g_wt[e * T_TOK + r]; }
        else         { s_tok[tid] = -1;                   s_w[tid] = 0.f; }
        s_bias[tid] = b1[(size_t)e * HIDDEN + n0 + tid];
    }
    __syncthreads();

    const __half* w1base = g_w1h + ((size_t)e * HIDDEN + n0) * D_MODEL;

    auto stage = [&](int buf, int k0) {
        const uint32_t ab = uS + (uint32_t)buf * 2 * TILE_B;
        const uint32_t bb = ab + TILE_B;
        #pragma unroll
        for (int i = 0; i < 8; i++) {
            int idx = tid + i * 128;
            int row = idx >> 3;
            int ch  = idx & 7;
            uint32_t soff = (uint32_t)(row * 128 + ((ch ^ (row & 7)) << 4));

            int pk  = s_tok[row];
            int tok = pk >= 0 ? (pk >> 1) : 0;
            cp16(ab + soff, g_xh + (size_t)tok * D_MODEL + k0 + ch * 8, pk >= 0 ? 16 : 0);
            cp16(bb + soff, w1base + (size_t)row * D_MODEL + k0 + ch * 8, 16);
        }
        asm volatile("cp.async.commit_group;" ::: "memory");
    };

    float acc[4][8][4];
    #pragma unroll
    for (int mt = 0; mt < 4; mt++)
        #pragma unroll
        for (int nt = 0; nt < 8; nt++)
            #pragma unroll
            for (int q = 0; q < 4; q++) acc[mt][nt][q] = 0.f;

    stage(0, 0);
    stage(1, BK);

    const int l8   = lid & 7;
    const int jA_m = ((lid >> 3) & 1) * 8;
    const int jA_k = (lid >> 4) & 1;
    const int jB_n = ((lid >> 4) & 1) * 8;
    const int jB_k = (lid >> 3) & 1;

    for (int c = 0; c < NCH; ++c) {
        asm volatile("cp.async.wait_group 1;" ::: "memory");
        __syncthreads();

        if (c + 2 < NCH) stage((c + 2) % STAGES, (c + 2) * BK);
        else asm volatile("cp.async.commit_group;" ::: "memory");  // keep 2 groups in flight

        const uint32_t ab = uS + (uint32_t)(c % STAGES) * 2 * TILE_B;
        const uint32_t bb = ab + TILE_B;

        #pragma unroll
        for (int s = 0; s < 4; s++) {
            uint32_t a[4][4];
            #pragma unroll
            for (int mt = 0; mt < 4; mt++) {
                int row = wm + mt * 16 + jA_m + l8;
                int ch  = 2 * s + jA_k;
                LDSM4(a[mt], ab + (uint32_t)(row * 128 + ((ch ^ (row & 7)) << 4)));
            }
            // interleave: load each B fragment, immediately issue its 8 MMAs
            #pragma unroll
            for (int bg = 0; bg < 4; bg++) {
                uint32_t bfr[4];
                int row = wn + bg * 16 + jB_n + l8;
                int ch  = 2 * s + jB_k;
                LDSM4(bfr, bb + (uint32_t)(row * 128 + ((ch ^ (row & 7)) << 4)));
                #pragma unroll
                for (int mt = 0; mt < 4; mt++) {
                    mma_f16(acc[mt][2 * bg + 0], a[mt], bfr + 0);
                    mma_f16(acc[mt][2 * bg + 1], a[mt], bfr + 2);
                }
            }
        }
    }

    const int lr = lid >> 2;
    const int lc = lid & 3;
    #pragma unroll
    for (int mt = 0; mt < 4; mt++) {
        int r_lo = wm + mt * 16 + lr;
        int r_hi = r_lo + 8;
        if ((m0 + r_lo) < cnt) {
            int   tok = s_tok[r_lo] >> 1;
            float wt  = s_w[r_lo];
            float* dst = out + (size_t)tok * HIDDEN + n0;
            #pragma unroll
            for (int nt = 0; nt < 8; nt++) {
                int col = wn + nt * 8 + lc * 2;
                red_add2(dst + col, wt * (acc[mt][nt][0] + s_bias[col]),
                                    wt * (acc[mt][nt][1] + s_bias[col + 1]));
            }
        }
        if ((m0 + r_hi) < cnt) {
            int   tok = s_tok[r_hi] >> 1;
            float wt  = s_w[r_hi];
            float* dst = out + (size_t)tok * HIDDEN + n0;
            #pragma unroll
            for (int nt = 0; nt < 8; nt++) {
                int col = wn + nt * 8 + lc * 2;
                red_add2(dst + col, wt * (acc[mt][nt][2] + s_bias[col]),
                                    wt * (acc[mt][nt][3] + s_bias[col + 1]));
            }
        }
    }

    __syncthreads();                // all warps done (reads + REDs issued)
    exit_ticket(tid);
}

// ---------------- launch ----------------
extern "C" void kernel_launch(void* const* d_in, const int* in_sizes, int n_in,
                              void* d_out, int out_size)
{
    const float* x  = (const float*)d_in[0];   // [1,2048,1024]
    const float* rw = (const float*)d_in[1];   // [8,1024]
    const float* w1 = (const float*)d_in[2];   // [8,4096,1024]
    const float* b1 = (const float*)d_in[3];   // [8,4096]
    float* out = (float*)d_out;

    static bool smem_set = false;
    if (!smem_set) {
        cudaFuncSetAttribute(moe_gemm_h, cudaFuncAttributeMaxDynamicSharedMemorySize,
                             STAGES * 2 * TILE_B);
        smem_set = true;
    }

    prep_kernel<<<NB_PREP, 256>>>(x, rw, w1, out);

    size_t total = (size_t)T_TOK * HIDDEN;
    int want_lbal = ((size_t)out_size > total) ? 1 : 0;

    dim3 gemm_grid(GRID_X, GRID_Y, GRID_Z);   // 16 mtiles, 32 ntiles + lbal slice, 8 experts
    moe_gemm_h<<<gemm_grid, 128, STAGES * 2 * TILE_B>>>(b1, out, want_lbal);
}